// round 1
// baseline (speedup 1.0000x reference)
#include <cuda_runtime.h>
#include <cuda_bf16.h>
#include <math.h>

// ---------------- problem constants ----------------
#define RR 64
#define CC 256
#define EE 768
#define HH 12
#define DD 64
#define FF 3072
#define MM (RR*CC)          // 16384 tokens

// ---------------- scratch (device globals; no allocation allowed) ----------------
__device__ float g_x  [MM*EE];
__device__ float g_h  [MM*EE];
__device__ float g_q  [MM*EE];
__device__ float g_k  [MM*EE];
__device__ float g_v  [MM*EE];
__device__ float g_ctx[MM*EE];
__device__ float g_aw [HH*CC*RR*RR];   // 3,145,728 floats; also covers row-attn (HH*CC*CC = 786,432)
__device__ float g_ffn[MM*FF];

// ---------------- layernorm: one block per token ----------------
__global__ void ln_kernel(const float* __restrict__ x, const float* __restrict__ s,
                          const float* __restrict__ b, float* __restrict__ out) {
    __shared__ float red[256];
    int t = threadIdx.x;
    const float* xr = x + (size_t)blockIdx.x * EE;
    float v0 = xr[t], v1 = xr[t + 256], v2 = xr[t + 512];
    red[t] = v0 + v1 + v2;
    __syncthreads();
    for (int o = 128; o; o >>= 1) { if (t < o) red[t] += red[t + o]; __syncthreads(); }
    float mean = red[0] * (1.0f / EE);
    __syncthreads();
    float d0 = v0 - mean, d1 = v1 - mean, d2 = v2 - mean;
    red[t] = d0 * d0 + d1 * d1 + d2 * d2;
    __syncthreads();
    for (int o = 128; o; o >>= 1) { if (t < o) red[t] += red[t + o]; __syncthreads(); }
    float rstd = rsqrtf(red[0] * (1.0f / EE) + 1e-6f);
    float* orow = out + (size_t)blockIdx.x * EE;
    orow[t      ] = d0 * rstd * s[t      ] + b[t      ];
    orow[t + 256] = d1 * rstd * s[t + 256] + b[t + 256];
    orow[t + 512] = d2 * rstd * s[t + 512] + b[t + 512];
}

// ---------------- gelu (tanh approx, as flax nn.gelu) ----------------
__device__ __forceinline__ float gelu_f(float x) {
    float x3 = x * x * x;
    return 0.5f * x * (1.0f + tanhf(0.7978845608028654f * (x + 0.044715f * x3)));
}

// ---------------- SGEMM: C = epi(A[MxK] @ B[KxN] + bias) (+res) ----------------
// 128x128 tile, BK=8, 256 threads, 8x8 micro-tile.
__global__ void __launch_bounds__(256) sgemm_kernel(
    const float* __restrict__ A, const float* __restrict__ B,
    const float* __restrict__ bias, const float* __restrict__ res,
    float* __restrict__ C, int M, int N, int K, float scale, int act_gelu)
{
    __shared__ float As[8][128];
    __shared__ float Bs[8][128];
    int tid = threadIdx.x;
    int m0 = blockIdx.y * 128, n0 = blockIdx.x * 128;

    int arow = tid >> 1, acol = (tid & 1) * 4;
    int brow = tid >> 5, bcol = (tid & 31) * 4;
    const float* Ag = A + (size_t)(m0 + arow) * K + acol;
    const float* Bg = B + (size_t)brow * N + n0 + bcol;

    int ty = tid >> 4, tx = tid & 15;
    float acc[8][8];
    #pragma unroll
    for (int i = 0; i < 8; i++)
        #pragma unroll
        for (int j = 0; j < 8; j++) acc[i][j] = 0.f;

    for (int k0 = 0; k0 < K; k0 += 8) {
        float4 va = *(const float4*)(Ag + k0);
        float4 vb = *(const float4*)(Bg + (size_t)k0 * N);
        As[acol + 0][arow] = va.x; As[acol + 1][arow] = va.y;
        As[acol + 2][arow] = va.z; As[acol + 3][arow] = va.w;
        *(float4*)&Bs[brow][bcol] = vb;
        __syncthreads();
        #pragma unroll
        for (int kk = 0; kk < 8; kk++) {
            float a[8], b[8];
            *(float4*)(a    ) = *(const float4*)&As[kk][ty * 8    ];
            *(float4*)(a + 4) = *(const float4*)&As[kk][ty * 8 + 4];
            *(float4*)(b    ) = *(const float4*)&Bs[kk][tx * 8    ];
            *(float4*)(b + 4) = *(const float4*)&Bs[kk][tx * 8 + 4];
            #pragma unroll
            for (int i = 0; i < 8; i++)
                #pragma unroll
                for (int j = 0; j < 8; j++)
                    acc[i][j] = fmaf(a[i], b[j], acc[i][j]);
        }
        __syncthreads();
    }

    #pragma unroll
    for (int i = 0; i < 8; i++) {
        int m = m0 + ty * 8 + i;
        #pragma unroll
        for (int j = 0; j < 8; j++) {
            int n = n0 + tx * 8 + j;
            float vv = (acc[i][j] + bias[n]) * scale;
            if (act_gelu) vv = gelu_f(vv);
            if (res) vv += res[(size_t)m * N + n];
            C[(size_t)m * N + n] = vv;
        }
    }
}

// ---------------- row attention scores: aw[h,i,j] = sum_{r,d} q[r,i,h,d]*k[r,j,h,d] ----------------
__global__ void __launch_bounds__(256) row_scores_kernel(
    const float* __restrict__ q, const float* __restrict__ k, float* __restrict__ aw)
{
    int h = blockIdx.z;
    int i0 = blockIdx.y * 32, j0 = blockIdx.x * 32;
    __shared__ float qs[32][65];
    __shared__ float ks[32][65];
    int tid = threadIdx.x;
    int ti = tid >> 4, tj = tid & 15;
    float a00 = 0.f, a01 = 0.f, a10 = 0.f, a11 = 0.f;

    for (int r = 0; r < RR; r++) {
        #pragma unroll
        for (int cc = 0; cc < 2; cc++) {
            int e4 = tid + 256 * cc;
            int row = e4 >> 4, col = (e4 & 15) * 4;
            float4 vq = *(const float4*)(q + ((size_t)((r * CC + i0 + row) * HH + h)) * DD + col);
            qs[row][col] = vq.x; qs[row][col + 1] = vq.y; qs[row][col + 2] = vq.z; qs[row][col + 3] = vq.w;
            float4 vk = *(const float4*)(k + ((size_t)((r * CC + j0 + row) * HH + h)) * DD + col);
            ks[row][col] = vk.x; ks[row][col + 1] = vk.y; ks[row][col + 2] = vk.z; ks[row][col + 3] = vk.w;
        }
        __syncthreads();
        #pragma unroll 8
        for (int d = 0; d < DD; d++) {
            float q0 = qs[ti * 2][d], q1 = qs[ti * 2 + 1][d];
            float k0v = ks[tj * 2][d], k1v = ks[tj * 2 + 1][d];
            a00 = fmaf(q0, k0v, a00); a01 = fmaf(q0, k1v, a01);
            a10 = fmaf(q1, k0v, a10); a11 = fmaf(q1, k1v, a11);
        }
        __syncthreads();
    }
    size_t base = (size_t)h * CC * CC;
    aw[base + (size_t)(i0 + ti * 2    ) * CC + j0 + tj * 2    ] = a00;
    aw[base + (size_t)(i0 + ti * 2    ) * CC + j0 + tj * 2 + 1] = a01;
    aw[base + (size_t)(i0 + ti * 2 + 1) * CC + j0 + tj * 2    ] = a10;
    aw[base + (size_t)(i0 + ti * 2 + 1) * CC + j0 + tj * 2 + 1] = a11;
}

// ---------------- softmax over 256-wide rows ----------------
__global__ void softmax256_kernel(float* __restrict__ p) {
    __shared__ float red[256];
    int t = threadIdx.x;
    float* pr = p + (size_t)blockIdx.x * 256;
    float v = pr[t];
    red[t] = v;
    __syncthreads();
    for (int o = 128; o; o >>= 1) { if (t < o) red[t] = fmaxf(red[t], red[t + o]); __syncthreads(); }
    float mx = red[0];
    __syncthreads();
    float e = expf(v - mx);
    red[t] = e;
    __syncthreads();
    for (int o = 128; o; o >>= 1) { if (t < o) red[t] += red[t + o]; __syncthreads(); }
    pr[t] = e / red[0];
}

// ---------------- row attention context: ctx[r,i,h,d] = sum_j p[h,i,j]*v[r,j,h,d] ----------------
__global__ void __launch_bounds__(256) row_ctx_kernel(
    const float* __restrict__ p, const float* __restrict__ v, float* __restrict__ ctx)
{
    int i0 = blockIdx.x * 32;
    int h = blockIdx.y;
    int r = blockIdx.z;
    int tid = threadIdx.x;
    int tx = tid & 63, ty = tid >> 6;      // tx = d, ty in 0..3
    __shared__ float ps[32][33];
    __shared__ float vs[32][65];
    float acc[8];
    #pragma unroll
    for (int u = 0; u < 8; u++) acc[u] = 0.f;

    for (int jc = 0; jc < CC; jc += 32) {
        {   // p tile 32i x 32j : one float4 per thread
            int row = tid >> 3, col = (tid & 7) * 4;
            float4 vp = *(const float4*)(p + (size_t)h * CC * CC + (size_t)(i0 + row) * CC + jc + col);
            ps[row][col] = vp.x; ps[row][col + 1] = vp.y; ps[row][col + 2] = vp.z; ps[row][col + 3] = vp.w;
        }
        #pragma unroll
        for (int cc = 0; cc < 2; cc++) {   // v tile 32j x 64d
            int e4 = tid + 256 * cc;
            int row = e4 >> 4, col = (e4 & 15) * 4;
            float4 vv = *(const float4*)(v + ((size_t)((r * CC + jc + row) * HH + h)) * DD + col);
            vs[row][col] = vv.x; vs[row][col + 1] = vv.y; vs[row][col + 2] = vv.z; vs[row][col + 3] = vv.w;
        }
        __syncthreads();
        #pragma unroll 8
        for (int j = 0; j < 32; j++) {
            float vv = vs[j][tx];
            #pragma unroll
            for (int u = 0; u < 8; u++)
                acc[u] = fmaf(ps[ty * 8 + u][j], vv, acc[u]);
        }
        __syncthreads();
    }
    #pragma unroll
    for (int u = 0; u < 8; u++)
        ctx[((size_t)((r * CC + i0 + ty * 8 + u) * HH + h)) * DD + tx] = acc[u];
}

// ---------------- column attention scores: aw2[h,c,i,j] = sum_d q[i,c,h,d]*k[j,c,h,d] ----------------
__global__ void __launch_bounds__(256) col_scores_kernel(
    const float* __restrict__ q, const float* __restrict__ k, float* __restrict__ aw)
{
    int c = blockIdx.x, h = blockIdx.y;
    __shared__ float qs[64][65];
    __shared__ float ks[64][65];
    int tid = threadIdx.x;
    #pragma unroll
    for (int c4 = 0; c4 < 4; c4++) {
        int e4 = tid + 256 * c4;
        int row = e4 >> 4, col = (e4 & 15) * 4;
        float4 vq = *(const float4*)(q + ((size_t)((row * CC + c) * HH + h)) * DD + col);
        qs[row][col] = vq.x; qs[row][col + 1] = vq.y; qs[row][col + 2] = vq.z; qs[row][col + 3] = vq.w;
        float4 vk = *(const float4*)(k + ((size_t)((row * CC + c) * HH + h)) * DD + col);
        ks[row][col] = vk.x; ks[row][col + 1] = vk.y; ks[row][col + 2] = vk.z; ks[row][col + 3] = vk.w;
    }
    __syncthreads();
    int j = tid & 63, ib = (tid >> 6) * 16;
    float acc[16];
    #pragma unroll
    for (int u = 0; u < 16; u++) acc[u] = 0.f;
    #pragma unroll 4
    for (int d = 0; d < DD; d++) {
        float kv = ks[j][d];
        #pragma unroll
        for (int u = 0; u < 16; u++)
            acc[u] = fmaf(qs[ib + u][d], kv, acc[u]);
    }
    size_t base = ((size_t)h * CC + c) * RR * RR;
    #pragma unroll
    for (int u = 0; u < 16; u++)
        aw[base + (size_t)(ib + u) * RR + j] = acc[u];
}

// ---------------- softmax over 64-wide rows (one warp per row) ----------------
__global__ void softmax64_kernel(float* __restrict__ p, int nrows) {
    int warp = (blockIdx.x * blockDim.x + threadIdx.x) >> 5;
    int lane = threadIdx.x & 31;
    if (warp >= nrows) return;
    float* pr = p + (size_t)warp * 64;
    float a = pr[lane], b = pr[lane + 32];
    float mx = fmaxf(a, b);
    #pragma unroll
    for (int o = 16; o; o >>= 1) mx = fmaxf(mx, __shfl_xor_sync(0xffffffffu, mx, o));
    a = expf(a - mx); b = expf(b - mx);
    float s = a + b;
    #pragma unroll
    for (int o = 16; o; o >>= 1) s += __shfl_xor_sync(0xffffffffu, s, o);
    float inv = 1.0f / s;
    pr[lane] = a * inv; pr[lane + 32] = b * inv;
}

// ---------------- column attention context: ctx[i,c,h,d] = sum_j p2[h,c,i,j]*v[j,c,h,d] ----------------
__global__ void __launch_bounds__(256) col_ctx_kernel(
    const float* __restrict__ p, const float* __restrict__ v, float* __restrict__ ctx)
{
    int c = blockIdx.x, h = blockIdx.y;
    __shared__ float ps[64][65];
    __shared__ float vs[64][65];
    int tid = threadIdx.x;
    size_t pbase = ((size_t)h * CC + c) * RR * RR;
    #pragma unroll
    for (int c4 = 0; c4 < 4; c4++) {
        int e4 = tid + 256 * c4;
        int row = e4 >> 4, col = (e4 & 15) * 4;
        float4 vp = *(const float4*)(p + pbase + (size_t)row * RR + col);
        ps[row][col] = vp.x; ps[row][col + 1] = vp.y; ps[row][col + 2] = vp.z; ps[row][col + 3] = vp.w;
        float4 vv = *(const float4*)(v + ((size_t)((row * CC + c) * HH + h)) * DD + col);
        vs[row][col] = vv.x; vs[row][col + 1] = vv.y; vs[row][col + 2] = vv.z; vs[row][col + 3] = vv.w;
    }
    __syncthreads();
    int d = tid & 63, ib = (tid >> 6) * 16;
    float acc[16];
    #pragma unroll
    for (int u = 0; u < 16; u++) acc[u] = 0.f;
    #pragma unroll 4
    for (int j = 0; j < RR; j++) {
        float vv = vs[j][d];
        #pragma unroll
        for (int u = 0; u < 16; u++)
            acc[u] = fmaf(ps[ib + u][j], vv, acc[u]);
    }
    #pragma unroll
    for (int u = 0; u < 16; u++)
        ctx[((size_t)(((ib + u) * CC + c) * HH + h)) * DD + d] = acc[u];
}

// ---------------- host driver ----------------
static void run_gemm(const float* A, const float* B, const float* bias, const float* res,
                     float* C, int M, int N, int K, float scale, int gelu) {
    dim3 grid(N / 128, M / 128);
    sgemm_kernel<<<grid, 256>>>(A, B, bias, res, C, M, N, K, scale, gelu);
}

extern "C" void kernel_launch(void* const* d_in, const int* in_sizes, int n_in,
                              void* d_out, int out_size) {
    const float* x_in = (const float*)d_in[0];
    const float* rq_w = (const float*)d_in[1];  const float* rq_b = (const float*)d_in[2];
    const float* rk_w = (const float*)d_in[3];  const float* rk_b = (const float*)d_in[4];
    const float* rv_w = (const float*)d_in[5];  const float* rv_b = (const float*)d_in[6];
    const float* ro_w = (const float*)d_in[7];  const float* ro_b = (const float*)d_in[8];
    const float* cq_w = (const float*)d_in[9];  const float* cq_b = (const float*)d_in[10];
    const float* ck_w = (const float*)d_in[11]; const float* ck_b = (const float*)d_in[12];
    const float* cv_w = (const float*)d_in[13]; const float* cv_b = (const float*)d_in[14];
    const float* co_w = (const float*)d_in[15]; const float* co_b = (const float*)d_in[16];
    const float* f1_w = (const float*)d_in[17]; const float* f1_b = (const float*)d_in[18];
    const float* f2_w = (const float*)d_in[19]; const float* f2_b = (const float*)d_in[20];
    const float* ln1_s = (const float*)d_in[21]; const float* ln1_b = (const float*)d_in[22];
    const float* ln2_s = (const float*)d_in[23]; const float* ln2_b = (const float*)d_in[24];
    const float* ln3_s = (const float*)d_in[25]; const float* ln3_b = (const float*)d_in[26];

    float *px, *ph, *pq, *pk, *pv, *pctx, *paw, *pffn;
    cudaGetSymbolAddress((void**)&px,   g_x);
    cudaGetSymbolAddress((void**)&ph,   g_h);
    cudaGetSymbolAddress((void**)&pq,   g_q);
    cudaGetSymbolAddress((void**)&pk,   g_k);
    cudaGetSymbolAddress((void**)&pv,   g_v);
    cudaGetSymbolAddress((void**)&pctx, g_ctx);
    cudaGetSymbolAddress((void**)&paw,  g_aw);
    cudaGetSymbolAddress((void**)&pffn, g_ffn);

    const float row_scale = 0.015625f;  // D^-0.5 * R^-0.5 = 1/8 * 1/8
    const float col_scale = 0.125f;     // D^-0.5

    // residual stream
    cudaMemcpyAsync(px, x_in, (size_t)MM * EE * sizeof(float), cudaMemcpyDeviceToDevice);

    // ===== row attention =====
    ln_kernel<<<MM, 256>>>(px, ln1_s, ln1_b, ph);
    run_gemm(ph, rq_w, rq_b, nullptr, pq, MM, EE, EE, row_scale, 0);
    run_gemm(ph, rk_w, rk_b, nullptr, pk, MM, EE, EE, 1.0f, 0);
    run_gemm(ph, rv_w, rv_b, nullptr, pv, MM, EE, EE, 1.0f, 0);
    { dim3 g(CC / 32, CC / 32, HH); row_scores_kernel<<<g, 256>>>(pq, pk, paw); }
    softmax256_kernel<<<HH * CC, 256>>>(paw);
    { dim3 g(CC / 32, HH, RR); row_ctx_kernel<<<g, 256>>>(paw, pv, pctx); }
    run_gemm(pctx, ro_w, ro_b, px, px, MM, EE, EE, 1.0f, 0);

    // ===== column attention =====
    ln_kernel<<<MM, 256>>>(px, ln2_s, ln2_b, ph);
    run_gemm(ph, cq_w, cq_b, nullptr, pq, MM, EE, EE, col_scale, 0);
    run_gemm(ph, ck_w, ck_b, nullptr, pk, MM, EE, EE, 1.0f, 0);
    run_gemm(ph, cv_w, cv_b, nullptr, pv, MM, EE, EE, 1.0f, 0);
    { dim3 g(CC, HH); col_scores_kernel<<<g, 256>>>(pq, pk, paw); }
    { int nrows = HH * CC * RR; softmax64_kernel<<<(nrows * 32 + 255) / 256, 256>>>(paw, nrows); }
    { dim3 g(CC, HH); col_ctx_kernel<<<g, 256>>>(paw, pv, pctx); }
    run_gemm(pctx, co_w, co_b, px, px, MM, EE, EE, 1.0f, 0);

    // ===== FFN =====
    ln_kernel<<<MM, 256>>>(px, ln3_s, ln3_b, ph);
    run_gemm(ph, f1_w, f1_b, nullptr, pffn, MM, FF, EE, 1.0f, 1);
    run_gemm(pffn, f2_w, f2_b, px, (float*)d_out, MM, EE, FF, 1.0f, 0);
}

// round 3
// speedup vs baseline: 2.7010x; 2.7010x over previous
#include <cuda_runtime.h>
#include <cuda_bf16.h>
#include <math.h>
#include <stdint.h>

// ---------------- problem constants ----------------
#define RR 64
#define CC 256
#define EE 768
#define HH 12
#define DD 64
#define FF 3072
#define MM (RR*CC)          // 16384 tokens

// ---------------- scratch (device globals; no allocation allowed) ----------------
__device__ float g_x  [MM*EE];
__device__ float g_h  [MM*EE];
__device__ float g_q  [MM*EE];
__device__ float g_k  [MM*EE];
__device__ float g_v  [MM*EE];
__device__ float g_ctx[MM*EE];
__device__ float g_aw [HH*CC*RR*RR];
__device__ float g_ffn[MM*FF];
__device__ float g_wt [9437184];   // transposed weights: 8*768*768 + 2*768*3072

// ---------------- helpers ----------------
__device__ __forceinline__ uint32_t smem_to_u32(const void* p) {
    uint32_t a;
    asm("{ .reg .u64 t; cvta.to.shared.u64 t, %1; cvt.u32.u64 %0, t; }" : "=r"(a) : "l"(p));
    return a;
}
__device__ __forceinline__ float to_tf32(float x) {
    float r; asm("cvt.rna.tf32.f32 %0, %1;" : "=f"(r) : "f"(x)); return r;
}
__device__ __forceinline__ void cp_async16(uint32_t saddr, const void* gptr) {
    asm volatile("cp.async.cg.shared.global [%0], [%1], 16;" :: "r"(saddr), "l"(gptr));
}
#define CP_COMMIT() asm volatile("cp.async.commit_group;" ::: "memory")
#define CP_WAIT1()  asm volatile("cp.async.wait_group 1;" ::: "memory")
#define CP_WAIT0()  asm volatile("cp.async.wait_group 0;" ::: "memory")

__device__ __forceinline__ void mma_tf32(float* d, const uint32_t* a, const uint32_t* b) {
    asm volatile("mma.sync.aligned.m16n8k8.row.col.f32.tf32.tf32.f32 "
        "{%0,%1,%2,%3}, {%4,%5,%6,%7}, {%8,%9}, {%0,%1,%2,%3};"
        : "+f"(d[0]), "+f"(d[1]), "+f"(d[2]), "+f"(d[3])
        : "r"(a[0]), "r"(a[1]), "r"(a[2]), "r"(a[3]), "r"(b[0]), "r"(b[1]));
}

// ---------------- gelu (tanh approx) ----------------
__device__ __forceinline__ float gelu_f(float x) {
    float x3 = x * x * x;
    return 0.5f * x * (1.0f + tanhf(0.7978845608028654f * (x + 0.044715f * x3)));
}

// ---------------- tf32 mma.sync GEMM: C = epi(A[MxK] @ BT[NxK]^T + bias) ----------------
// 128x128 block tile, BK=32, 256 threads = 8 warps in 4(m) x 2(n); warp tile 32x64.
#define BK 32
#define PITCH 36   // floats per smem row (pad 4 to kill bank conflicts)
#define TILE_F (128 * PITCH)

__global__ void __launch_bounds__(256) mma_gemm_kernel(
    const float* __restrict__ A, const float* __restrict__ BT,
    const float* __restrict__ bias, const float* __restrict__ res,
    float* __restrict__ C, int M, int N, int K,
    float scale, int act_gelu, int round_out)
{
    extern __shared__ float sm[];
    float* Abuf[2] = { sm,              sm + TILE_F };
    float* Bbuf[2] = { sm + 2 * TILE_F, sm + 3 * TILE_F };
    uint32_t sbase = smem_to_u32(sm);
    uint32_t AbufU[2] = { sbase,                     sbase + TILE_F * 4 };
    uint32_t BbufU[2] = { sbase + 2 * TILE_F * 4,    sbase + 3 * TILE_F * 4 };

    int tid = threadIdx.x;
    int wid = tid >> 5, lane = tid & 31;
    int g = lane >> 2, t = lane & 3;
    int wm = wid & 3, wn = wid >> 2;          // warp coords: 4 x 2
    int m0 = blockIdx.y * 128, n0 = blockIdx.x * 128;

    float acc[2][8][4];
    #pragma unroll
    for (int i = 0; i < 2; i++)
        #pragma unroll
        for (int j = 0; j < 8; j++)
            #pragma unroll
            for (int c = 0; c < 4; c++) acc[i][j][c] = 0.f;

    const int NT = K / BK;

    // prefetch helper (lambda-free for regs): A rows = m tile, B rows = n tile, both [row][k]
    #define PREFETCH(kt, b) do {                                               \
        int k0p = (kt) * BK;                                                   \
        _Pragma("unroll")                                                      \
        for (int i = 0; i < 4; i++) {                                          \
            int idx = i * 256 + tid;                                           \
            int row = idx >> 3, c4 = (idx & 7) * 4;                            \
            cp_async16(AbufU[b] + (uint32_t)(row * PITCH + c4) * 4,            \
                       A  + (size_t)(m0 + row) * K + k0p + c4);                \
            cp_async16(BbufU[b] + (uint32_t)(row * PITCH + c4) * 4,            \
                       BT + (size_t)(n0 + row) * K + k0p + c4);                \
        }                                                                      \
        CP_COMMIT();                                                           \
    } while (0)

    PREFETCH(0, 0);
    if (NT > 1) PREFETCH(1, 1);

    for (int kt = 0; kt < NT; kt++) {
        int b = kt & 1;
        if (kt + 1 < NT) CP_WAIT1(); else CP_WAIT0();
        __syncthreads();

        const float* As = Abuf[b];
        const float* Bs = Bbuf[b];
        int arow0 = (wm * 32 + g) * PITCH;
        int brow0 = (wn * 64 + g) * PITCH;

        #pragma unroll
        for (int ks = 0; ks < 4; ks++) {
            int k0 = ks * 8;
            uint32_t af[2][4], bf[8][2];
            #pragma unroll
            for (int mt = 0; mt < 2; mt++) {
                int r = arow0 + mt * 16 * PITCH;
                af[mt][0] = __float_as_uint(As[r + k0 + t]);
                af[mt][1] = __float_as_uint(As[r + 8 * PITCH + k0 + t]);
                af[mt][2] = __float_as_uint(As[r + k0 + t + 4]);
                af[mt][3] = __float_as_uint(As[r + 8 * PITCH + k0 + t + 4]);
            }
            #pragma unroll
            for (int nt = 0; nt < 8; nt++) {
                int r = brow0 + nt * 8 * PITCH;
                bf[nt][0] = __float_as_uint(Bs[r + k0 + t]);
                bf[nt][1] = __float_as_uint(Bs[r + k0 + t + 4]);
            }
            #pragma unroll
            for (int mt = 0; mt < 2; mt++)
                #pragma unroll
                for (int nt = 0; nt < 8; nt++)
                    mma_tf32(acc[mt][nt], af[mt], bf[nt]);
        }
        __syncthreads();
        if (kt + 2 < NT) PREFETCH(kt + 2, b);
    }
    #undef PREFETCH

    // epilogue: regs -> global with bias/scale/gelu/res
    #pragma unroll
    for (int mt = 0; mt < 2; mt++) {
        #pragma unroll
        for (int nt = 0; nt < 8; nt++) {
            int m = m0 + wm * 32 + mt * 16 + g;
            int n = n0 + wn * 64 + nt * 8 + 2 * t;
            float bx = bias[n], by = bias[n + 1];
            #pragma unroll
            for (int half = 0; half < 2; half++) {
                int mr = m + half * 8;
                float vx = (acc[mt][nt][half * 2 + 0] + bx) * scale;
                float vy = (acc[mt][nt][half * 2 + 1] + by) * scale;
                if (act_gelu) { vx = gelu_f(vx); vy = gelu_f(vy); }
                if (res) {
                    const float2 r2 = *(const float2*)(res + (size_t)mr * N + n);
                    vx += r2.x; vy += r2.y;
                }
                if (round_out) { vx = to_tf32(vx); vy = to_tf32(vy); }
                float2 o; o.x = vx; o.y = vy;
                *(float2*)(C + (size_t)mr * N + n) = o;
            }
        }
    }
}

// ---------------- transpose: W[K][N] -> WT[N][K], tf32-rounded ----------------
__global__ void transpose_kernel(const float* __restrict__ in, float* __restrict__ out, int K, int N) {
    __shared__ float tbuf[32][33];
    int x = blockIdx.x * 32 + threadIdx.x;
    int y0 = blockIdx.y * 32;
    #pragma unroll
    for (int i = threadIdx.y; i < 32; i += 8)
        tbuf[i][threadIdx.x] = in[(size_t)(y0 + i) * N + x];
    __syncthreads();
    int xo = blockIdx.y * 32 + threadIdx.x;
    int yo0 = blockIdx.x * 32;
    #pragma unroll
    for (int i = threadIdx.y; i < 32; i += 8)
        out[(size_t)(yo0 + i) * K + xo] = to_tf32(tbuf[threadIdx.x][i]);
}

// ---------------- layernorm: one block per token (output tf32-rounded: GEMM input only) ----------------
__global__ void ln_kernel(const float* __restrict__ x, const float* __restrict__ s,
                          const float* __restrict__ b, float* __restrict__ out) {
    __shared__ float red[256];
    int t = threadIdx.x;
    const float* xr = x + (size_t)blockIdx.x * EE;
    float v0 = xr[t], v1 = xr[t + 256], v2 = xr[t + 512];
    red[t] = v0 + v1 + v2;
    __syncthreads();
    for (int o = 128; o; o >>= 1) { if (t < o) red[t] += red[t + o]; __syncthreads(); }
    float mean = red[0] * (1.0f / EE);
    __syncthreads();
    float d0 = v0 - mean, d1 = v1 - mean, d2 = v2 - mean;
    red[t] = d0 * d0 + d1 * d1 + d2 * d2;
    __syncthreads();
    for (int o = 128; o; o >>= 1) { if (t < o) red[t] += red[t + o]; __syncthreads(); }
    float rstd = rsqrtf(red[0] * (1.0f / EE) + 1e-6f);
    float* orow = out + (size_t)blockIdx.x * EE;
    orow[t      ] = to_tf32(d0 * rstd * s[t      ] + b[t      ]);
    orow[t + 256] = to_tf32(d1 * rstd * s[t + 256] + b[t + 256]);
    orow[t + 512] = to_tf32(d2 * rstd * s[t + 512] + b[t + 512]);
}

// ---------------- row attention scores ----------------
__global__ void __launch_bounds__(256) row_scores_kernel(
    const float* __restrict__ q, const float* __restrict__ k, float* __restrict__ aw)
{
    int h = blockIdx.z;
    int i0 = blockIdx.y * 32, j0 = blockIdx.x * 32;
    __shared__ float qs[32][65];
    __shared__ float ks[32][65];
    int tid = threadIdx.x;
    int ti = tid >> 4, tj = tid & 15;
    float a00 = 0.f, a01 = 0.f, a10 = 0.f, a11 = 0.f;

    for (int r = 0; r < RR; r++) {
        #pragma unroll
        for (int cc = 0; cc < 2; cc++) {
            int e4 = tid + 256 * cc;
            int row = e4 >> 4, col = (e4 & 15) * 4;
            float4 vq = *(const float4*)(q + ((size_t)((r * CC + i0 + row) * HH + h)) * DD + col);
            qs[row][col] = vq.x; qs[row][col + 1] = vq.y; qs[row][col + 2] = vq.z; qs[row][col + 3] = vq.w;
            float4 vk = *(const float4*)(k + ((size_t)((r * CC + j0 + row) * HH + h)) * DD + col);
            ks[row][col] = vk.x; ks[row][col + 1] = vk.y; ks[row][col + 2] = vk.z; ks[row][col + 3] = vk.w;
        }
        __syncthreads();
        #pragma unroll 8
        for (int d = 0; d < DD; d++) {
            float q0 = qs[ti * 2][d], q1 = qs[ti * 2 + 1][d];
            float k0v = ks[tj * 2][d], k1v = ks[tj * 2 + 1][d];
            a00 = fmaf(q0, k0v, a00); a01 = fmaf(q0, k1v, a01);
            a10 = fmaf(q1, k0v, a10); a11 = fmaf(q1, k1v, a11);
        }
        __syncthreads();
    }
    size_t bbase = (size_t)h * CC * CC;
    aw[bbase + (size_t)(i0 + ti * 2    ) * CC + j0 + tj * 2    ] = a00;
    aw[bbase + (size_t)(i0 + ti * 2    ) * CC + j0 + tj * 2 + 1] = a01;
    aw[bbase + (size_t)(i0 + ti * 2 + 1) * CC + j0 + tj * 2    ] = a10;
    aw[bbase + (size_t)(i0 + ti * 2 + 1) * CC + j0 + tj * 2 + 1] = a11;
}

// ---------------- softmax over 256-wide rows ----------------
__global__ void softmax256_kernel(float* __restrict__ p) {
    __shared__ float red[256];
    int t = threadIdx.x;
    float* pr = p + (size_t)blockIdx.x * 256;
    float v = pr[t];
    red[t] = v;
    __syncthreads();
    for (int o = 128; o; o >>= 1) { if (t < o) red[t] = fmaxf(red[t], red[t + o]); __syncthreads(); }
    float mx = red[0];
    __syncthreads();
    float e = expf(v - mx);
    red[t] = e;
    __syncthreads();
    for (int o = 128; o; o >>= 1) { if (t < o) red[t] += red[t + o]; __syncthreads(); }
    pr[t] = e / red[0];
}

// ---------------- row attention context (output tf32: GEMM input only) ----------------
__global__ void __launch_bounds__(256) row_ctx_kernel(
    const float* __restrict__ p, const float* __restrict__ v, float* __restrict__ ctx)
{
    int i0 = blockIdx.x * 32;
    int h = blockIdx.y;
    int r = blockIdx.z;
    int tid = threadIdx.x;
    int tx = tid & 63, ty = tid >> 6;
    __shared__ float ps[32][33];
    __shared__ float vs[32][65];
    float acc[8];
    #pragma unroll
    for (int u = 0; u < 8; u++) acc[u] = 0.f;

    for (int jc = 0; jc < CC; jc += 32) {
        {
            int row = tid >> 3, col = (tid & 7) * 4;
            float4 vp = *(const float4*)(p + (size_t)h * CC * CC + (size_t)(i0 + row) * CC + jc + col);
            ps[row][col] = vp.x; ps[row][col + 1] = vp.y; ps[row][col + 2] = vp.z; ps[row][col + 3] = vp.w;
        }
        #pragma unroll
        for (int cc = 0; cc < 2; cc++) {
            int e4 = tid + 256 * cc;
            int row = e4 >> 4, col = (e4 & 15) * 4;
            float4 vv = *(const float4*)(v + ((size_t)((r * CC + jc + row) * HH + h)) * DD + col);
            vs[row][col] = vv.x; vs[row][col + 1] = vv.y; vs[row][col + 2] = vv.z; vs[row][col + 3] = vv.w;
        }
        __syncthreads();
        #pragma unroll 8
        for (int j = 0; j < 32; j++) {
            float vv = vs[j][tx];
            #pragma unroll
            for (int u = 0; u < 8; u++)
                acc[u] = fmaf(ps[ty * 8 + u][j], vv, acc[u]);
        }
        __syncthreads();
    }
    #pragma unroll
    for (int u = 0; u < 8; u++)
        ctx[((size_t)((r * CC + i0 + ty * 8 + u) * HH + h)) * DD + tx] = to_tf32(acc[u]);
}

// ---------------- column attention scores ----------------
__global__ void __launch_bounds__(256) col_scores_kernel(
    const float* __restrict__ q, const float* __restrict__ k, float* __restrict__ aw)
{
    int c = blockIdx.x, h = blockIdx.y;
    __shared__ float qs[64][65];
    __shared__ float ks[64][65];
    int tid = threadIdx.x;
    #pragma unroll
    for (int c4 = 0; c4 < 4; c4++) {
        int e4 = tid + 256 * c4;
        int row = e4 >> 4, col = (e4 & 15) * 4;
        float4 vq = *(const float4*)(q + ((size_t)((row * CC + c) * HH + h)) * DD + col);
        qs[row][col] = vq.x; qs[row][col + 1] = vq.y; qs[row][col + 2] = vq.z; qs[row][col + 3] = vq.w;
        float4 vk = *(const float4*)(k + ((size_t)((row * CC + c) * HH + h)) * DD + col);
        ks[row][col] = vk.x; ks[row][col + 1] = vk.y; ks[row][col + 2] = vk.z; ks[row][col + 3] = vk.w;
    }
    __syncthreads();
    int j = tid & 63, ib = (tid >> 6) * 16;
    float acc[16];
    #pragma unroll
    for (int u = 0; u < 16; u++) acc[u] = 0.f;
    #pragma unroll 4
    for (int d = 0; d < DD; d++) {
        float kv = ks[j][d];
        #pragma unroll
        for (int u = 0; u < 16; u++)
            acc[u] = fmaf(qs[ib + u][d], kv, acc[u]);
    }
    size_t bbase = ((size_t)h * CC + c) * RR * RR;
    #pragma unroll
    for (int u = 0; u < 16; u++)
        aw[bbase + (size_t)(ib + u) * RR + j] = acc[u];
}

// ---------------- softmax over 64-wide rows ----------------
__global__ void softmax64_kernel(float* __restrict__ p, int nrows) {
    int warp = (blockIdx.x * blockDim.x + threadIdx.x) >> 5;
    int lane = threadIdx.x & 31;
    if (warp >= nrows) return;
    float* pr = p + (size_t)warp * 64;
    float a = pr[lane], b = pr[lane + 32];
    float mx = fmaxf(a, b);
    #pragma unroll
    for (int o = 16; o; o >>= 1) mx = fmaxf(mx, __shfl_xor_sync(0xffffffffu, mx, o));
    a = expf(a - mx); b = expf(b - mx);
    float s = a + b;
    #pragma unroll
    for (int o = 16; o; o >>= 1) s += __shfl_xor_sync(0xffffffffu, s, o);
    float inv = 1.0f / s;
    pr[lane] = a * inv; pr[lane + 32] = b * inv;
}

// ---------------- column attention context (output tf32: GEMM input only) ----------------
__global__ void __launch_bounds__(256) col_ctx_kernel(
    const float* __restrict__ p, const float* __restrict__ v, float* __restrict__ ctx)
{
    int c = blockIdx.x, h = blockIdx.y;
    __shared__ float ps[64][65];
    __shared__ float vs[64][65];
    int tid = threadIdx.x;
    size_t pbase = ((size_t)h * CC + c) * RR * RR;
    #pragma unroll
    for (int c4 = 0; c4 < 4; c4++) {
        int e4 = tid + 256 * c4;
        int row = e4 >> 4, col = (e4 & 15) * 4;
        float4 vp = *(const float4*)(p + pbase + (size_t)row * RR + col);
        ps[row][col] = vp.x; ps[row][col + 1] = vp.y; ps[row][col + 2] = vp.z; ps[row][col + 3] = vp.w;
        float4 vv = *(const float4*)(v + ((size_t)((row * CC + c) * HH + h)) * DD + col);
        vs[row][col] = vv.x; vs[row][col + 1] = vv.y; vs[row][col + 2] = vv.z; vs[row][col + 3] = vv.w;
    }
    __syncthreads();
    int d = tid & 63, ib = (tid >> 6) * 16;
    float acc[16];
    #pragma unroll
    for (int u = 0; u < 16; u++) acc[u] = 0.f;
    #pragma unroll 4
    for (int j = 0; j < RR; j++) {
        float vv = vs[j][d];
        #pragma unroll
        for (int u = 0; u < 16; u++)
            acc[u] = fmaf(ps[ib + u][j], vv, acc[u]);
    }
    #pragma unroll
    for (int u = 0; u < 16; u++)
        ctx[((size_t)(((ib + u) * CC + c) * HH + h)) * DD + d] = to_tf32(acc[u]);
}

// ---------------- host driver ----------------
#define GEMM_SMEM (4 * TILE_F * 4)   // 73728 bytes

static void run_gemm(const float* A, const float* BT, const float* bias, const float* res,
                     float* C, int M, int N, int K, float scale, int gelu, int round_out) {
    dim3 grid(N / 128, M / 128);
    mma_gemm_kernel<<<grid, 256, GEMM_SMEM>>>(A, BT, bias, res, C, M, N, K, scale, gelu, round_out);
}

extern "C" void kernel_launch(void* const* d_in, const int* in_sizes, int n_in,
                              void* d_out, int out_size) {
    const float* x_in = (const float*)d_in[0];
    const float* rq_w = (const float*)d_in[1];  const float* rq_b = (const float*)d_in[2];
    const float* rk_w = (const float*)d_in[3];  const float* rk_b = (const float*)d_in[4];
    const float* rv_w = (const float*)d_in[5];  const float* rv_b = (const float*)d_in[6];
    const float* ro_w = (const float*)d_in[7];  const float* ro_b = (const float*)d_in[8];
    const float* cq_w = (const float*)d_in[9];  const float* cq_b = (const float*)d_in[10];
    const float* ck_w = (const float*)d_in[11]; const float* ck_b = (const float*)d_in[12];
    const float* cv_w = (const float*)d_in[13]; const float* cv_b = (const float*)d_in[14];
    const float* co_w = (const float*)d_in[15]; const float* co_b = (const float*)d_in[16];
    const float* f1_w = (const float*)d_in[17]; const float* f1_b = (const float*)d_in[18];
    const float* f2_w = (const float*)d_in[19]; const float* f2_b = (const float*)d_in[20];
    const float* ln1_s = (const float*)d_in[21]; const float* ln1_b = (const float*)d_in[22];
    const float* ln2_s = (const float*)d_in[23]; const float* ln2_b = (const float*)d_in[24];
    const float* ln3_s = (const float*)d_in[25]; const float* ln3_b = (const float*)d_in[26];

    float *px, *ph, *pq, *pk, *pv, *pctx, *paw, *pffn, *pwt;
    cudaGetSymbolAddress((void**)&px,   g_x);
    cudaGetSymbolAddress((void**)&ph,   g_h);
    cudaGetSymbolAddress((void**)&pq,   g_q);
    cudaGetSymbolAddress((void**)&pk,   g_k);
    cudaGetSymbolAddress((void**)&pv,   g_v);
    cudaGetSymbolAddress((void**)&pctx, g_ctx);
    cudaGetSymbolAddress((void**)&paw,  g_aw);
    cudaGetSymbolAddress((void**)&pffn, g_ffn);
    cudaGetSymbolAddress((void**)&pwt,  g_wt);

    cudaFuncSetAttribute(mma_gemm_kernel, cudaFuncAttributeMaxDynamicSharedMemorySize, GEMM_SMEM);

    // transposed (and tf32-rounded) weights in g_wt
    const size_t WEE = (size_t)EE * EE;
    float* rqT = pwt + 0 * WEE;  float* rkT = pwt + 1 * WEE;
    float* rvT = pwt + 2 * WEE;  float* roT = pwt + 3 * WEE;
    float* cqT = pwt + 4 * WEE;  float* ckT = pwt + 5 * WEE;
    float* cvT = pwt + 6 * WEE;  float* coT = pwt + 7 * WEE;
    float* f1T = pwt + 8 * WEE;                     // [F][E]
    float* f2T = f1T + (size_t)EE * FF;             // [E][F]

    { dim3 b(32, 8);
      dim3 gE(EE / 32, EE / 32);
      transpose_kernel<<<gE, b>>>(rq_w, rqT, EE, EE);
      transpose_kernel<<<gE, b>>>(rk_w, rkT, EE, EE);
      transpose_kernel<<<gE, b>>>(rv_w, rvT, EE, EE);
      transpose_kernel<<<gE, b>>>(ro_w, roT, EE, EE);
      transpose_kernel<<<gE, b>>>(cq_w, cqT, EE, EE);
      transpose_kernel<<<gE, b>>>(ck_w, ckT, EE, EE);
      transpose_kernel<<<gE, b>>>(cv_w, cvT, EE, EE);
      transpose_kernel<<<gE, b>>>(co_w, coT, EE, EE);
      dim3 gF1(FF / 32, EE / 32);
      transpose_kernel<<<gF1, b>>>(f1_w, f1T, EE, FF);
      dim3 gF2(EE / 32, FF / 32);
      transpose_kernel<<<gF2, b>>>(f2_w, f2T, FF, EE);
    }

    const float row_scale = 0.015625f;  // D^-0.5 * R^-0.5
    const float col_scale = 0.125f;     // D^-0.5

    cudaMemcpyAsync(px, x_in, (size_t)MM * EE * sizeof(float), cudaMemcpyDeviceToDevice);

    // ===== row attention =====
    ln_kernel<<<MM, 256>>>(px, ln1_s, ln1_b, ph);
    run_gemm(ph, rqT, rq_b, nullptr, pq, MM, EE, EE, row_scale, 0, 0);
    run_gemm(ph, rkT, rk_b, nullptr, pk, MM, EE, EE, 1.0f, 0, 0);
    run_gemm(ph, rvT, rv_b, nullptr, pv, MM, EE, EE, 1.0f, 0, 0);
    { dim3 g(CC / 32, CC / 32, HH); row_scores_kernel<<<g, 256>>>(pq, pk, paw); }
    softmax256_kernel<<<HH * CC, 256>>>(paw);
    { dim3 g(CC / 32, HH, RR); row_ctx_kernel<<<g, 256>>>(paw, pv, pctx); }
    run_gemm(pctx, roT, ro_b, px, px, MM, EE, EE, 1.0f, 0, 0);

    // ===== column attention =====
    ln_kernel<<<MM, 256>>>(px, ln2_s, ln2_b, ph);
    run_gemm(ph, cqT, cq_b, nullptr, pq, MM, EE, EE, col_scale, 0, 0);
    run_gemm(ph, ckT, ck_b, nullptr, pk, MM, EE, EE, 1.0f, 0, 0);
    run_gemm(ph, cvT, cv_b, nullptr, pv, MM, EE, EE, 1.0f, 0, 0);
    { dim3 g(CC, HH); col_scores_kernel<<<g, 256>>>(pq, pk, paw); }
    { int nrows = HH * CC * RR; softmax64_kernel<<<(nrows * 32 + 255) / 256, 256>>>(paw, nrows); }
    { dim3 g(CC, HH); col_ctx_kernel<<<g, 256>>>(paw, pv, pctx); }
    run_gemm(pctx, coT, co_b, px, px, MM, EE, EE, 1.0f, 0, 0);

    // ===== FFN =====
    ln_kernel<<<MM, 256>>>(px, ln3_s, ln3_b, ph);
    run_gemm(ph, f1T, f1_b, nullptr, pffn, MM, FF, EE, 1.0f, 1, 1);   // gelu + tf32-round (GEMM input)
    run_gemm(pffn, f2T, f2_b, px, (float*)d_out, MM, EE, FF, 1.0f, 0, 0);
}

// round 4
// speedup vs baseline: 2.7077x; 1.0025x over previous
#include <cuda_runtime.h>
#include <cuda_bf16.h>
#include <math.h>
#include <stdint.h>

// ---------------- problem constants ----------------
#define RR 64
#define CC 256
#define EE 768
#define HH 12
#define DD 64
#define FF 3072
#define MM (RR*CC)          // 16384 tokens

// ---------------- scratch (device globals; no allocation allowed) ----------------
__device__ float g_x  [MM*EE];
__device__ float g_h  [MM*EE];
__device__ float g_q  [MM*EE];
__device__ float g_k  [MM*EE];
__device__ float g_v  [MM*EE];
__device__ float g_ctx[MM*EE];
__device__ float g_aw [HH*CC*RR*RR];
__device__ float g_ffn[MM*FF];
__device__ float g_wt [9437184];   // transposed weights: 8*768*768 + 2*768*3072

// ---------------- helpers ----------------
__device__ __forceinline__ uint32_t smem_to_u32(const void* p) {
    uint32_t a;
    asm("{ .reg .u64 t; cvta.to.shared.u64 t, %1; cvt.u32.u64 %0, t; }" : "=r"(a) : "l"(p));
    return a;
}
__device__ __forceinline__ float to_tf32(float x) {
    float r; asm("cvt.rna.tf32.f32 %0, %1;" : "=f"(r) : "f"(x)); return r;
}
__device__ __forceinline__ void cp_async16(uint32_t saddr, const void* gptr) {
    asm volatile("cp.async.cg.shared.global [%0], [%1], 16;" :: "r"(saddr), "l"(gptr));
}
#define CP_COMMIT() asm volatile("cp.async.commit_group;" ::: "memory")
#define CP_WAIT1()  asm volatile("cp.async.wait_group 1;" ::: "memory")
#define CP_WAIT0()  asm volatile("cp.async.wait_group 0;" ::: "memory")

__device__ __forceinline__ void ldsm_x4(uint32_t* r, uint32_t addr) {
    asm volatile("ldmatrix.sync.aligned.m8n8.x4.shared.b16 {%0,%1,%2,%3}, [%4];"
        : "=r"(r[0]), "=r"(r[1]), "=r"(r[2]), "=r"(r[3]) : "r"(addr));
}

__device__ __forceinline__ void mma_tf32(float* d, const uint32_t* a, uint32_t b0, uint32_t b1) {
    asm volatile("mma.sync.aligned.m16n8k8.row.col.f32.tf32.tf32.f32 "
        "{%0,%1,%2,%3}, {%4,%5,%6,%7}, {%8,%9}, {%0,%1,%2,%3};"
        : "+f"(d[0]), "+f"(d[1]), "+f"(d[2]), "+f"(d[3])
        : "r"(a[0]), "r"(a[1]), "r"(a[2]), "r"(a[3]), "r"(b0), "r"(b1));
}

// ---------------- gelu (tanh approx) ----------------
__device__ __forceinline__ float gelu_f(float x) {
    float x3 = x * x * x;
    return 0.5f * x * (1.0f + tanhf(0.7978845608028654f * (x + 0.044715f * x3)));
}

// ---------------- tf32 mma.sync GEMM: C = epi(A[MxK] @ BT[NxK]^T + bias) ----------------
// 128x128 block tile, BK=32, 256 threads = 8 warps in 4(m) x 2(n); warp tile 32x64.
// 3-stage cp.async pipeline; ldmatrix.x4 fragment loads.
#define BK 32
#define PITCH 36   // floats per smem row (144B: 8-row ldmatrix covers all 32 banks)
#define TILE_F (128 * PITCH)
#define NSTAGE 3

__global__ void __launch_bounds__(256) mma_gemm_kernel(
    const float* __restrict__ A, const float* __restrict__ BT,
    const float* __restrict__ bias, const float* __restrict__ res,
    float* __restrict__ C, int M, int N, int K,
    float scale, int act_gelu, int round_out)
{
    extern __shared__ float sm[];
    uint32_t sbase = smem_to_u32(sm);
    uint32_t AbufU[NSTAGE], BbufU[NSTAGE];
    #pragma unroll
    for (int s = 0; s < NSTAGE; s++) {
        AbufU[s] = sbase + (uint32_t)(2 * s    ) * TILE_F * 4;
        BbufU[s] = sbase + (uint32_t)(2 * s + 1) * TILE_F * 4;
    }

    int tid = threadIdx.x;
    int wid = tid >> 5, lane = tid & 31;
    int g = lane >> 2, t = lane & 3;
    int wm = wid & 3, wn = wid >> 2;          // warp coords: 4 x 2
    int m0 = blockIdx.y * 128, n0 = blockIdx.x * 128;

    // ldmatrix lane offsets (bytes within a tile buffer)
    int m4 = lane >> 3;          // matrix id 0..3
    int rin = lane & 7;
    int roff = ((m4 & 1) << 3) + rin;      // row within 16-row group
    uint32_t kb16 = (uint32_t)(m4 >> 1) * 16;  // +16B for k+4 matrices
    uint32_t offA[2], offB[4];
    #pragma unroll
    for (int mt = 0; mt < 2; mt++)
        offA[mt] = (uint32_t)((wm * 32 + mt * 16 + roff) * PITCH) * 4 + kb16;
    #pragma unroll
    for (int p = 0; p < 4; p++)
        offB[p] = (uint32_t)((wn * 64 + p * 16 + roff) * PITCH) * 4 + kb16;

    float acc[2][8][4];
    #pragma unroll
    for (int i = 0; i < 2; i++)
        #pragma unroll
        for (int j = 0; j < 8; j++)
            #pragma unroll
            for (int c = 0; c < 4; c++) acc[i][j][c] = 0.f;

    const int NT = K / BK;

    #define PREFETCH(kt, b) do {                                               \
        int k0p = (kt) * BK;                                                   \
        _Pragma("unroll")                                                      \
        for (int i = 0; i < 4; i++) {                                          \
            int idx = i * 256 + tid;                                           \
            int row = idx >> 3, c4 = (idx & 7) * 4;                            \
            cp_async16(AbufU[b] + (uint32_t)(row * PITCH + c4) * 4,            \
                       A  + (size_t)(m0 + row) * K + k0p + c4);                \
            cp_async16(BbufU[b] + (uint32_t)(row * PITCH + c4) * 4,            \
                       BT + (size_t)(n0 + row) * K + k0p + c4);                \
        }                                                                      \
        CP_COMMIT();                                                           \
    } while (0)

    PREFETCH(0, 0);
    if (NT > 1) PREFETCH(1, 1);

    for (int kt = 0; kt < NT; kt++) {
        int b = kt % NSTAGE;
        if (kt + 1 < NT) CP_WAIT1(); else CP_WAIT0();
        __syncthreads();
        if (kt + 2 < NT) PREFETCH(kt + 2, (kt + 2) % NSTAGE);

        uint32_t Ab = AbufU[b], Bb = BbufU[b];
        #pragma unroll
        for (int ks = 0; ks < 4; ks++) {
            uint32_t koff = (uint32_t)ks * 32;
            uint32_t af[2][4], bfr[4][4];
            ldsm_x4(af[0], Ab + offA[0] + koff);
            ldsm_x4(af[1], Ab + offA[1] + koff);
            #pragma unroll
            for (int p = 0; p < 4; p++)
                ldsm_x4(bfr[p], Bb + offB[p] + koff);
            #pragma unroll
            for (int mt = 0; mt < 2; mt++)
                #pragma unroll
                for (int nt = 0; nt < 8; nt++) {
                    const uint32_t* Bp = bfr[nt >> 1];
                    uint32_t b0 = (nt & 1) ? Bp[1] : Bp[0];
                    uint32_t b1 = (nt & 1) ? Bp[3] : Bp[2];
                    mma_tf32(acc[mt][nt], af[mt], b0, b1);
                }
        }
        __syncthreads();
    }
    #undef PREFETCH

    // epilogue: regs -> global with bias/scale/gelu/res
    #pragma unroll
    for (int mt = 0; mt < 2; mt++) {
        #pragma unroll
        for (int nt = 0; nt < 8; nt++) {
            int m = m0 + wm * 32 + mt * 16 + g;
            int n = n0 + wn * 64 + nt * 8 + 2 * t;
            float bx = bias[n], by = bias[n + 1];
            #pragma unroll
            for (int half = 0; half < 2; half++) {
                int mr = m + half * 8;
                float vx = (acc[mt][nt][half * 2 + 0] + bx) * scale;
                float vy = (acc[mt][nt][half * 2 + 1] + by) * scale;
                if (act_gelu) { vx = gelu_f(vx); vy = gelu_f(vy); }
                if (res) {
                    const float2 r2 = *(const float2*)(res + (size_t)mr * N + n);
                    vx += r2.x; vy += r2.y;
                }
                if (round_out) { vx = to_tf32(vx); vy = to_tf32(vy); }
                float2 o; o.x = vx; o.y = vy;
                *(float2*)(C + (size_t)mr * N + n) = o;
            }
        }
    }
}

// ---------------- transpose: W[K][N] -> WT[N][K], tf32-rounded ----------------
__global__ void transpose_kernel(const float* __restrict__ in, float* __restrict__ out, int K, int N) {
    __shared__ float tbuf[32][33];
    int x = blockIdx.x * 32 + threadIdx.x;
    int y0 = blockIdx.y * 32;
    #pragma unroll
    for (int i = threadIdx.y; i < 32; i += 8)
        tbuf[i][threadIdx.x] = in[(size_t)(y0 + i) * N + x];
    __syncthreads();
    int xo = blockIdx.y * 32 + threadIdx.x;
    int yo0 = blockIdx.x * 32;
    #pragma unroll
    for (int i = threadIdx.y; i < 32; i += 8)
        out[(size_t)(yo0 + i) * K + xo] = to_tf32(tbuf[threadIdx.x][i]);
}

// ---------------- layernorm: one block per token (output tf32-rounded: GEMM input only) ----------------
__global__ void ln_kernel(const float* __restrict__ x, const float* __restrict__ s,
                          const float* __restrict__ b, float* __restrict__ out) {
    __shared__ float red[256];
    int t = threadIdx.x;
    const float* xr = x + (size_t)blockIdx.x * EE;
    float v0 = xr[t], v1 = xr[t + 256], v2 = xr[t + 512];
    red[t] = v0 + v1 + v2;
    __syncthreads();
    for (int o = 128; o; o >>= 1) { if (t < o) red[t] += red[t + o]; __syncthreads(); }
    float mean = red[0] * (1.0f / EE);
    __syncthreads();
    float d0 = v0 - mean, d1 = v1 - mean, d2 = v2 - mean;
    red[t] = d0 * d0 + d1 * d1 + d2 * d2;
    __syncthreads();
    for (int o = 128; o; o >>= 1) { if (t < o) red[t] += red[t + o]; __syncthreads(); }
    float rstd = rsqrtf(red[0] * (1.0f / EE) + 1e-6f);
    float* orow = out + (size_t)blockIdx.x * EE;
    orow[t      ] = to_tf32(d0 * rstd * s[t      ] + b[t      ]);
    orow[t + 256] = to_tf32(d1 * rstd * s[t + 256] + b[t + 256]);
    orow[t + 512] = to_tf32(d2 * rstd * s[t + 512] + b[t + 512]);
}

// ---------------- row attention scores ----------------
__global__ void __launch_bounds__(256) row_scores_kernel(
    const float* __restrict__ q, const float* __restrict__ k, float* __restrict__ aw)
{
    int h = blockIdx.z;
    int i0 = blockIdx.y * 32, j0 = blockIdx.x * 32;
    __shared__ float qs[32][65];
    __shared__ float ks[32][65];
    int tid = threadIdx.x;
    int ti = tid >> 4, tj = tid & 15;
    float a00 = 0.f, a01 = 0.f, a10 = 0.f, a11 = 0.f;

    for (int r = 0; r < RR; r++) {
        #pragma unroll
        for (int cc = 0; cc < 2; cc++) {
            int e4 = tid + 256 * cc;
            int row = e4 >> 4, col = (e4 & 15) * 4;
            float4 vq = *(const float4*)(q + ((size_t)((r * CC + i0 + row) * HH + h)) * DD + col);
            qs[row][col] = vq.x; qs[row][col + 1] = vq.y; qs[row][col + 2] = vq.z; qs[row][col + 3] = vq.w;
            float4 vk = *(const float4*)(k + ((size_t)((r * CC + j0 + row) * HH + h)) * DD + col);
            ks[row][col] = vk.x; ks[row][col + 1] = vk.y; ks[row][col + 2] = vk.z; ks[row][col + 3] = vk.w;
        }
        __syncthreads();
        #pragma unroll 8
        for (int d = 0; d < DD; d++) {
            float q0 = qs[ti * 2][d], q1 = qs[ti * 2 + 1][d];
            float k0v = ks[tj * 2][d], k1v = ks[tj * 2 + 1][d];
            a00 = fmaf(q0, k0v, a00); a01 = fmaf(q0, k1v, a01);
            a10 = fmaf(q1, k0v, a10); a11 = fmaf(q1, k1v, a11);
        }
        __syncthreads();
    }
    size_t bbase = (size_t)h * CC * CC;
    aw[bbase + (size_t)(i0 + ti * 2    ) * CC + j0 + tj * 2    ] = a00;
    aw[bbase + (size_t)(i0 + ti * 2    ) * CC + j0 + tj * 2 + 1] = a01;
    aw[bbase + (size_t)(i0 + ti * 2 + 1) * CC + j0 + tj * 2    ] = a10;
    aw[bbase + (size_t)(i0 + ti * 2 + 1) * CC + j0 + tj * 2 + 1] = a11;
}

// ---------------- softmax over 256-wide rows ----------------
__global__ void softmax256_kernel(float* __restrict__ p) {
    __shared__ float red[256];
    int t = threadIdx.x;
    float* pr = p + (size_t)blockIdx.x * 256;
    float v = pr[t];
    red[t] = v;
    __syncthreads();
    for (int o = 128; o; o >>= 1) { if (t < o) red[t] = fmaxf(red[t], red[t + o]); __syncthreads(); }
    float mx = red[0];
    __syncthreads();
    float e = expf(v - mx);
    red[t] = e;
    __syncthreads();
    for (int o = 128; o; o >>= 1) { if (t < o) red[t] += red[t + o]; __syncthreads(); }
    pr[t] = e / red[0];
}

// ---------------- row attention context (output tf32: GEMM input only) ----------------
__global__ void __launch_bounds__(256) row_ctx_kernel(
    const float* __restrict__ p, const float* __restrict__ v, float* __restrict__ ctx)
{
    int i0 = blockIdx.x * 32;
    int h = blockIdx.y;
    int r = blockIdx.z;
    int tid = threadIdx.x;
    int tx = tid & 63, ty = tid >> 6;
    __shared__ float ps[32][33];
    __shared__ float vs[32][65];
    float acc[8];
    #pragma unroll
    for (int u = 0; u < 8; u++) acc[u] = 0.f;

    for (int jc = 0; jc < CC; jc += 32) {
        {
            int row = tid >> 3, col = (tid & 7) * 4;
            float4 vp = *(const float4*)(p + (size_t)h * CC * CC + (size_t)(i0 + row) * CC + jc + col);
            ps[row][col] = vp.x; ps[row][col + 1] = vp.y; ps[row][col + 2] = vp.z; ps[row][col + 3] = vp.w;
        }
        #pragma unroll
        for (int cc = 0; cc < 2; cc++) {
            int e4 = tid + 256 * cc;
            int row = e4 >> 4, col = (e4 & 15) * 4;
            float4 vv = *(const float4*)(v + ((size_t)((r * CC + jc + row) * HH + h)) * DD + col);
            vs[row][col] = vv.x; vs[row][col + 1] = vv.y; vs[row][col + 2] = vv.z; vs[row][col + 3] = vv.w;
        }
        __syncthreads();
        #pragma unroll 8
        for (int j = 0; j < 32; j++) {
            float vv = vs[j][tx];
            #pragma unroll
            for (int u = 0; u < 8; u++)
                acc[u] = fmaf(ps[ty * 8 + u][j], vv, acc[u]);
        }
        __syncthreads();
    }
    #pragma unroll
    for (int u = 0; u < 8; u++)
        ctx[((size_t)((r * CC + i0 + ty * 8 + u) * HH + h)) * DD + tx] = to_tf32(acc[u]);
}

// ---------------- column attention scores ----------------
__global__ void __launch_bounds__(256) col_scores_kernel(
    const float* __restrict__ q, const float* __restrict__ k, float* __restrict__ aw)
{
    int c = blockIdx.x, h = blockIdx.y;
    __shared__ float qs[64][65];
    __shared__ float ks[64][65];
    int tid = threadIdx.x;
    #pragma unroll
    for (int c4 = 0; c4 < 4; c4++) {
        int e4 = tid + 256 * c4;
        int row = e4 >> 4, col = (e4 & 15) * 4;
        float4 vq = *(const float4*)(q + ((size_t)((row * CC + c) * HH + h)) * DD + col);
        qs[row][col] = vq.x; qs[row][col + 1] = vq.y; qs[row][col + 2] = vq.z; qs[row][col + 3] = vq.w;
        float4 vk = *(const float4*)(k + ((size_t)((row * CC + c) * HH + h)) * DD + col);
        ks[row][col] = vk.x; ks[row][col + 1] = vk.y; ks[row][col + 2] = vk.z; ks[row][col + 3] = vk.w;
    }
    __syncthreads();
    int j = tid & 63, ib = (tid >> 6) * 16;
    float acc[16];
    #pragma unroll
    for (int u = 0; u < 16; u++) acc[u] = 0.f;
    #pragma unroll 4
    for (int d = 0; d < DD; d++) {
        float kv = ks[j][d];
        #pragma unroll
        for (int u = 0; u < 16; u++)
            acc[u] = fmaf(qs[ib + u][d], kv, acc[u]);
    }
    size_t bbase = ((size_t)h * CC + c) * RR * RR;
    #pragma unroll
    for (int u = 0; u < 16; u++)
        aw[bbase + (size_t)(ib + u) * RR + j] = acc[u];
}

// ---------------- softmax over 64-wide rows ----------------
__global__ void softmax64_kernel(float* __restrict__ p, int nrows) {
    int warp = (blockIdx.x * blockDim.x + threadIdx.x) >> 5;
    int lane = threadIdx.x & 31;
    if (warp >= nrows) return;
    float* pr = p + (size_t)warp * 64;
    float a = pr[lane], b = pr[lane + 32];
    float mx = fmaxf(a, b);
    #pragma unroll
    for (int o = 16; o; o >>= 1) mx = fmaxf(mx, __shfl_xor_sync(0xffffffffu, mx, o));
    a = expf(a - mx); b = expf(b - mx);
    float s = a + b;
    #pragma unroll
    for (int o = 16; o; o >>= 1) s += __shfl_xor_sync(0xffffffffu, s, o);
    float inv = 1.0f / s;
    pr[lane] = a * inv; pr[lane + 32] = b * inv;
}

// ---------------- column attention context (output tf32: GEMM input only) ----------------
__global__ void __launch_bounds__(256) col_ctx_kernel(
    const float* __restrict__ p, const float* __restrict__ v, float* __restrict__ ctx)
{
    int c = blockIdx.x, h = blockIdx.y;
    __shared__ float ps[64][65];
    __shared__ float vs[64][65];
    int tid = threadIdx.x;
    size_t pbase = ((size_t)h * CC + c) * RR * RR;
    #pragma unroll
    for (int c4 = 0; c4 < 4; c4++) {
        int e4 = tid + 256 * c4;
        int row = e4 >> 4, col = (e4 & 15) * 4;
        float4 vp = *(const float4*)(p + pbase + (size_t)row * RR + col);
        ps[row][col] = vp.x; ps[row][col + 1] = vp.y; ps[row][col + 2] = vp.z; ps[row][col + 3] = vp.w;
        float4 vv = *(const float4*)(v + ((size_t)((row * CC + c) * HH + h)) * DD + col);
        vs[row][col] = vv.x; vs[row][col + 1] = vv.y; vs[row][col + 2] = vv.z; vs[row][col + 3] = vv.w;
    }
    __syncthreads();
    int d = tid & 63, ib = (tid >> 6) * 16;
    float acc[16];
    #pragma unroll
    for (int u = 0; u < 16; u++) acc[u] = 0.f;
    #pragma unroll 4
    for (int j = 0; j < RR; j++) {
        float vv = vs[j][d];
        #pragma unroll
        for (int u = 0; u < 16; u++)
            acc[u] = fmaf(ps[ib + u][j], vv, acc[u]);
    }
    #pragma unroll
    for (int u = 0; u < 16; u++)
        ctx[((size_t)(((ib + u) * CC + c) * HH + h)) * DD + d] = to_tf32(acc[u]);
}

// ---------------- host driver ----------------
#define GEMM_SMEM (NSTAGE * 2 * TILE_F * 4)   // 110592 bytes

static void run_gemm(const float* A, const float* BT, const float* bias, const float* res,
                     float* C, int M, int N, int K, float scale, int gelu, int round_out) {
    dim3 grid(N / 128, M / 128);
    mma_gemm_kernel<<<grid, 256, GEMM_SMEM>>>(A, BT, bias, res, C, M, N, K, scale, gelu, round_out);
}

extern "C" void kernel_launch(void* const* d_in, const int* in_sizes, int n_in,
                              void* d_out, int out_size) {
    const float* x_in = (const float*)d_in[0];
    const float* rq_w = (const float*)d_in[1];  const float* rq_b = (const float*)d_in[2];
    const float* rk_w = (const float*)d_in[3];  const float* rk_b = (const float*)d_in[4];
    const float* rv_w = (const float*)d_in[5];  const float* rv_b = (const float*)d_in[6];
    const float* ro_w = (const float*)d_in[7];  const float* ro_b = (const float*)d_in[8];
    const float* cq_w = (const float*)d_in[9];  const float* cq_b = (const float*)d_in[10];
    const float* ck_w = (const float*)d_in[11]; const float* ck_b = (const float*)d_in[12];
    const float* cv_w = (const float*)d_in[13]; const float* cv_b = (const float*)d_in[14];
    const float* co_w = (const float*)d_in[15]; const float* co_b = (const float*)d_in[16];
    const float* f1_w = (const float*)d_in[17]; const float* f1_b = (const float*)d_in[18];
    const float* f2_w = (const float*)d_in[19]; const float* f2_b = (const float*)d_in[20];
    const float* ln1_s = (const float*)d_in[21]; const float* ln1_b = (const float*)d_in[22];
    const float* ln2_s = (const float*)d_in[23]; const float* ln2_b = (const float*)d_in[24];
    const float* ln3_s = (const float*)d_in[25]; const float* ln3_b = (const float*)d_in[26];

    float *px, *ph, *pq, *pk, *pv, *pctx, *paw, *pffn, *pwt;
    cudaGetSymbolAddress((void**)&px,   g_x);
    cudaGetSymbolAddress((void**)&ph,   g_h);
    cudaGetSymbolAddress((void**)&pq,   g_q);
    cudaGetSymbolAddress((void**)&pk,   g_k);
    cudaGetSymbolAddress((void**)&pv,   g_v);
    cudaGetSymbolAddress((void**)&pctx, g_ctx);
    cudaGetSymbolAddress((void**)&paw,  g_aw);
    cudaGetSymbolAddress((void**)&pffn, g_ffn);
    cudaGetSymbolAddress((void**)&pwt,  g_wt);

    cudaFuncSetAttribute(mma_gemm_kernel, cudaFuncAttributeMaxDynamicSharedMemorySize, GEMM_SMEM);

    // transposed (and tf32-rounded) weights in g_wt
    const size_t WEE = (size_t)EE * EE;
    float* rqT = pwt + 0 * WEE;  float* rkT = pwt + 1 * WEE;
    float* rvT = pwt + 2 * WEE;  float* roT = pwt + 3 * WEE;
    float* cqT = pwt + 4 * WEE;  float* ckT = pwt + 5 * WEE;
    float* cvT = pwt + 6 * WEE;  float* coT = pwt + 7 * WEE;
    float* f1T = pwt + 8 * WEE;                     // [F][E]
    float* f2T = f1T + (size_t)EE * FF;             // [E][F]

    { dim3 b(32, 8);
      dim3 gE(EE / 32, EE / 32);
      transpose_kernel<<<gE, b>>>(rq_w, rqT, EE, EE);
      transpose_kernel<<<gE, b>>>(rk_w, rkT, EE, EE);
      transpose_kernel<<<gE, b>>>(rv_w, rvT, EE, EE);
      transpose_kernel<<<gE, b>>>(ro_w, roT, EE, EE);
      transpose_kernel<<<gE, b>>>(cq_w, cqT, EE, EE);
      transpose_kernel<<<gE, b>>>(ck_w, ckT, EE, EE);
      transpose_kernel<<<gE, b>>>(cv_w, cvT, EE, EE);
      transpose_kernel<<<gE, b>>>(co_w, coT, EE, EE);
      dim3 gF1(FF / 32, EE / 32);
      transpose_kernel<<<gF1, b>>>(f1_w, f1T, EE, FF);
      dim3 gF2(EE / 32, FF / 32);
      transpose_kernel<<<gF2, b>>>(f2_w, f2T, FF, EE);
    }

    const float row_scale = 0.015625f;  // D^-0.5 * R^-0.5
    const float col_scale = 0.125f;     // D^-0.5

    cudaMemcpyAsync(px, x_in, (size_t)MM * EE * sizeof(float), cudaMemcpyDeviceToDevice);

    // ===== row attention =====
    ln_kernel<<<MM, 256>>>(px, ln1_s, ln1_b, ph);
    run_gemm(ph, rqT, rq_b, nullptr, pq, MM, EE, EE, row_scale, 0, 0);
    run_gemm(ph, rkT, rk_b, nullptr, pk, MM, EE, EE, 1.0f, 0, 0);
    run_gemm(ph, rvT, rv_b, nullptr, pv, MM, EE, EE, 1.0f, 0, 0);
    { dim3 g(CC / 32, CC / 32, HH); row_scores_kernel<<<g, 256>>>(pq, pk, paw); }
    softmax256_kernel<<<HH * CC, 256>>>(paw);
    { dim3 g(CC / 32, HH, RR); row_ctx_kernel<<<g, 256>>>(paw, pv, pctx); }
    run_gemm(pctx, roT, ro_b, px, px, MM, EE, EE, 1.0f, 0, 0);

    // ===== column attention =====
    ln_kernel<<<MM, 256>>>(px, ln2_s, ln2_b, ph);
    run_gemm(ph, cqT, cq_b, nullptr, pq, MM, EE, EE, col_scale, 0, 0);
    run_gemm(ph, ckT, ck_b, nullptr, pk, MM, EE, EE, 1.0f, 0, 0);
    run_gemm(ph, cvT, cv_b, nullptr, pv, MM, EE, EE, 1.0f, 0, 0);
    { dim3 g(CC, HH); col_scores_kernel<<<g, 256>>>(pq, pk, paw); }
    { int nrows = HH * CC * RR; softmax64_kernel<<<(nrows * 32 + 255) / 256, 256>>>(paw, nrows); }
    { dim3 g(CC, HH); col_ctx_kernel<<<g, 256>>>(paw, pv, pctx); }
    run_gemm(pctx, coT, co_b, px, px, MM, EE, EE, 1.0f, 0, 0);

    // ===== FFN =====
    ln_kernel<<<MM, 256>>>(px, ln3_s, ln3_b, ph);
    run_gemm(ph, f1T, f1_b, nullptr, pffn, MM, FF, EE, 1.0f, 1, 1);   // gelu + tf32-round (GEMM input)
    run_gemm(pffn, f2T, f2_b, px, (float*)d_out, MM, EE, FF, 1.0f, 0, 0);
}

// round 5
// speedup vs baseline: 3.7605x; 1.3888x over previous
#include <cuda_runtime.h>
#include <cuda_fp16.h>
#include <math.h>
#include <stdint.h>

// ---------------- problem constants ----------------
#define RR 64
#define CC 256
#define EE 768
#define HH 12
#define DD 64
#define FF 3072
#define MM (RR*CC)          // 16384 tokens

// ---------------- scratch (device globals; no allocation allowed) ----------------
__device__ float g_x  [MM*EE];       // residual stream (fp32)
__device__ float g_h  [MM*EE];       // reused as __half
__device__ float g_q  [MM*EE];       // reused as __half
__device__ float g_k  [MM*EE];       // reused as __half
__device__ float g_v  [MM*EE];       // reused as __half
__device__ float g_ctx[MM*EE];       // reused as __half
__device__ float g_aw [HH*CC*RR*RR]; // fp32 attention weights
__device__ float g_ffn[MM*FF];       // reused as __half
__device__ float g_wt [9437184/2 + 64];  // transposed half weights (9.4M halves)

// ---------------- helpers ----------------
__device__ __forceinline__ uint32_t smem_to_u32(const void* p) {
    uint32_t a;
    asm("{ .reg .u64 t; cvta.to.shared.u64 t, %1; cvt.u32.u64 %0, t; }" : "=r"(a) : "l"(p));
    return a;
}
__device__ __forceinline__ void cp_async16(uint32_t saddr, const void* gptr) {
    asm volatile("cp.async.cg.shared.global [%0], [%1], 16;" :: "r"(saddr), "l"(gptr));
}
#define CP_COMMIT() asm volatile("cp.async.commit_group;" ::: "memory")
#define CP_WAIT1()  asm volatile("cp.async.wait_group 1;" ::: "memory")
#define CP_WAIT0()  asm volatile("cp.async.wait_group 0;" ::: "memory")

__device__ __forceinline__ void ldsm_x4(uint32_t* r, uint32_t addr) {
    asm volatile("ldmatrix.sync.aligned.m8n8.x4.shared.b16 {%0,%1,%2,%3}, [%4];"
        : "=r"(r[0]), "=r"(r[1]), "=r"(r[2]), "=r"(r[3]) : "r"(addr));
}

__device__ __forceinline__ void mma_f16(float* d, const uint32_t* a, uint32_t b0, uint32_t b1) {
    asm volatile("mma.sync.aligned.m16n8k16.row.col.f32.f16.f16.f32 "
        "{%0,%1,%2,%3}, {%4,%5,%6,%7}, {%8,%9}, {%0,%1,%2,%3};"
        : "+f"(d[0]), "+f"(d[1]), "+f"(d[2]), "+f"(d[3])
        : "r"(a[0]), "r"(a[1]), "r"(a[2]), "r"(a[3]), "r"(b0), "r"(b1));
}

// ---------------- gelu (tanh approx) ----------------
__device__ __forceinline__ float gelu_f(float x) {
    float x3 = x * x * x;
    return 0.5f * x * (1.0f + tanhf(0.7978845608028654f * (x + 0.044715f * x3)));
}

// ---------------- fp16 mma.sync GEMM: out = epi(A[MxK] @ BT[NxK]^T + bias) ----------------
// 128x128 tile, BK=32 halves, 256 threads = 8 warps (4m x 2n), warp tile 32x64.
#define BKH 32
#define PITCH_H 40            // halves per smem row (80B: conflict-free ldmatrix)
#define TILE_H (128 * PITCH_H)
#define NSTAGE 3

__global__ void __launch_bounds__(256) mma_gemm_f16(
    const __half* __restrict__ A, const __half* __restrict__ BT,
    const float* __restrict__ bias, const float* __restrict__ res,
    float* __restrict__ Cf, __half* __restrict__ Ch,
    int M, int N, int K, float scale, int act_gelu)
{
    extern __shared__ __half smh[];
    uint32_t sbase = smem_to_u32(smh);
    uint32_t AbufU[NSTAGE], BbufU[NSTAGE];
    #pragma unroll
    for (int s = 0; s < NSTAGE; s++) {
        AbufU[s] = sbase + (uint32_t)(2 * s    ) * TILE_H * 2;
        BbufU[s] = sbase + (uint32_t)(2 * s + 1) * TILE_H * 2;
    }

    int tid = threadIdx.x;
    int wid = tid >> 5, lane = tid & 31;
    int g = lane >> 2, t = lane & 3;
    int wm = wid & 3, wn = wid >> 2;
    int m0 = blockIdx.y * 128, n0 = blockIdx.x * 128;

    // ldmatrix byte offsets within a tile buffer
    int l16 = lane & 15;
    uint32_t a_koff = (uint32_t)(lane >> 4) * 16;    // second 8-half chunk
    uint32_t offA[2];
    #pragma unroll
    for (int mt = 0; mt < 2; mt++)
        offA[mt] = (uint32_t)((wm * 32 + mt * 16 + l16) * PITCH_H) * 2 + a_koff;
    int l8 = lane & 7;
    int b_half16 = (lane >> 3) & 1;                  // k chunk select
    int b_grp8 = lane >> 4;                          // n subgroup select
    uint32_t offB[4];
    #pragma unroll
    for (int p = 0; p < 4; p++)
        offB[p] = (uint32_t)((wn * 64 + p * 16 + b_grp8 * 8 + l8) * PITCH_H) * 2 + (uint32_t)b_half16 * 16;

    float acc[2][8][4];
    #pragma unroll
    for (int i = 0; i < 2; i++)
        #pragma unroll
        for (int j = 0; j < 8; j++)
            #pragma unroll
            for (int c = 0; c < 4; c++) acc[i][j][c] = 0.f;

    const int NT = K / BKH;

    #define PREFETCH(kt, b) do {                                               \
        int k0p = (kt) * BKH;                                                  \
        _Pragma("unroll")                                                      \
        for (int i = 0; i < 2; i++) {                                          \
            int idx = i * 256 + tid;                                           \
            int row = idx >> 2, c8 = (idx & 3) * 8;                            \
            cp_async16(AbufU[b] + (uint32_t)(row * PITCH_H + c8) * 2,          \
                       A  + (size_t)(m0 + row) * K + k0p + c8);                \
            cp_async16(BbufU[b] + (uint32_t)(row * PITCH_H + c8) * 2,          \
                       BT + (size_t)(n0 + row) * K + k0p + c8);                \
        }                                                                      \
        CP_COMMIT();                                                           \
    } while (0)

    PREFETCH(0, 0);
    if (NT > 1) PREFETCH(1, 1);

    for (int kt = 0; kt < NT; kt++) {
        int b = kt % NSTAGE;
        if (kt + 1 < NT) CP_WAIT1(); else CP_WAIT0();
        __syncthreads();
        if (kt + 2 < NT) PREFETCH(kt + 2, (kt + 2) % NSTAGE);

        uint32_t Ab = AbufU[b], Bb = BbufU[b];
        #pragma unroll
        for (int ks = 0; ks < 2; ks++) {           // two k16 steps per BK=32
            uint32_t koff = (uint32_t)ks * 32;     // 16 halves
            uint32_t af[2][4], bfr[4][4];
            ldsm_x4(af[0], Ab + offA[0] + koff);
            ldsm_x4(af[1], Ab + offA[1] + koff);
            #pragma unroll
            for (int p = 0; p < 4; p++)
                ldsm_x4(bfr[p], Bb + offB[p] + koff);
            #pragma unroll
            for (int mt = 0; mt < 2; mt++)
                #pragma unroll
                for (int p = 0; p < 4; p++) {
                    mma_f16(acc[mt][2 * p    ], af[mt], bfr[p][0], bfr[p][1]);
                    mma_f16(acc[mt][2 * p + 1], af[mt], bfr[p][2], bfr[p][3]);
                }
        }
        __syncthreads();
    }
    #undef PREFETCH

    // epilogue
    #pragma unroll
    for (int mt = 0; mt < 2; mt++) {
        #pragma unroll
        for (int nt = 0; nt < 8; nt++) {
            int m = m0 + wm * 32 + mt * 16 + g;
            int n = n0 + wn * 64 + nt * 8 + 2 * t;
            float bx = bias[n], by = bias[n + 1];
            #pragma unroll
            for (int half = 0; half < 2; half++) {
                int mr = m + half * 8;
                float vx = (acc[mt][nt][half * 2 + 0] + bx) * scale;
                float vy = (acc[mt][nt][half * 2 + 1] + by) * scale;
                if (act_gelu) { vx = gelu_f(vx); vy = gelu_f(vy); }
                if (res) {
                    const float2 r2 = *(const float2*)(res + (size_t)mr * N + n);
                    vx += r2.x; vy += r2.y;
                }
                if (Cf) {
                    float2 o; o.x = vx; o.y = vy;
                    *(float2*)(Cf + (size_t)mr * N + n) = o;
                } else {
                    *(__half2*)(Ch + (size_t)mr * N + n) = __floats2half2_rn(vx, vy);
                }
            }
        }
    }
}

// ---------------- transpose: W[K][N] fp32 -> WT[N][K] half ----------------
__global__ void transpose_kernel(const float* __restrict__ in, __half* __restrict__ out, int K, int N) {
    __shared__ float tbuf[32][33];
    int x = blockIdx.x * 32 + threadIdx.x;
    int y0 = blockIdx.y * 32;
    #pragma unroll
    for (int i = threadIdx.y; i < 32; i += 8)
        tbuf[i][threadIdx.x] = in[(size_t)(y0 + i) * N + x];
    __syncthreads();
    int xo = blockIdx.y * 32 + threadIdx.x;
    int yo0 = blockIdx.x * 32;
    #pragma unroll
    for (int i = threadIdx.y; i < 32; i += 8)
        out[(size_t)(yo0 + i) * K + xo] = __float2half(tbuf[threadIdx.x][i]);
}

// ---------------- layernorm: fp32 in, half out ----------------
__global__ void ln_kernel(const float* __restrict__ x, const float* __restrict__ s,
                          const float* __restrict__ b, __half* __restrict__ out) {
    __shared__ float red[256];
    int t = threadIdx.x;
    const float* xr = x + (size_t)blockIdx.x * EE;
    float v0 = xr[t], v1 = xr[t + 256], v2 = xr[t + 512];
    red[t] = v0 + v1 + v2;
    __syncthreads();
    for (int o = 128; o; o >>= 1) { if (t < o) red[t] += red[t + o]; __syncthreads(); }
    float mean = red[0] * (1.0f / EE);
    __syncthreads();
    float d0 = v0 - mean, d1 = v1 - mean, d2 = v2 - mean;
    red[t] = d0 * d0 + d1 * d1 + d2 * d2;
    __syncthreads();
    for (int o = 128; o; o >>= 1) { if (t < o) red[t] += red[t + o]; __syncthreads(); }
    float rstd = rsqrtf(red[0] * (1.0f / EE) + 1e-6f);
    __half* orow = out + (size_t)blockIdx.x * EE;
    orow[t      ] = __float2half(d0 * rstd * s[t      ] + b[t      ]);
    orow[t + 256] = __float2half(d1 * rstd * s[t + 256] + b[t + 256]);
    orow[t + 512] = __float2half(d2 * rstd * s[t + 512] + b[t + 512]);
}

// unpack 8 halves (uint4) into smem row
__device__ __forceinline__ void unpack8(float* dst, uint4 raw) {
    __half2* hp = (__half2*)&raw;
    #pragma unroll
    for (int j = 0; j < 4; j++) {
        float2 f = __half22float2(hp[j]);
        dst[2 * j] = f.x; dst[2 * j + 1] = f.y;
    }
}

// ---------------- row attention scores: aw[h,i,j] = sum_{r,d} q*k ----------------
__global__ void __launch_bounds__(256) row_scores_kernel(
    const __half* __restrict__ q, const __half* __restrict__ k, float* __restrict__ aw)
{
    int h = blockIdx.z;
    int i0 = blockIdx.y * 32, j0 = blockIdx.x * 32;
    __shared__ float qs[32][65];
    __shared__ float ks[32][65];
    int tid = threadIdx.x;
    int ti = tid >> 4, tj = tid & 15;
    float a00 = 0.f, a01 = 0.f, a10 = 0.f, a11 = 0.f;

    int lrow = tid >> 3, lcol = (tid & 7) * 8;
    for (int r = 0; r < RR; r++) {
        uint4 rq = *(const uint4*)(q + ((size_t)((r * CC + i0 + lrow) * HH + h)) * DD + lcol);
        unpack8(&qs[lrow][lcol], rq);
        uint4 rk = *(const uint4*)(k + ((size_t)((r * CC + j0 + lrow) * HH + h)) * DD + lcol);
        unpack8(&ks[lrow][lcol], rk);
        __syncthreads();
        #pragma unroll 8
        for (int d = 0; d < DD; d++) {
            float q0 = qs[ti * 2][d], q1 = qs[ti * 2 + 1][d];
            float k0v = ks[tj * 2][d], k1v = ks[tj * 2 + 1][d];
            a00 = fmaf(q0, k0v, a00); a01 = fmaf(q0, k1v, a01);
            a10 = fmaf(q1, k0v, a10); a11 = fmaf(q1, k1v, a11);
        }
        __syncthreads();
    }
    size_t bbase = (size_t)h * CC * CC;
    aw[bbase + (size_t)(i0 + ti * 2    ) * CC + j0 + tj * 2    ] = a00;
    aw[bbase + (size_t)(i0 + ti * 2    ) * CC + j0 + tj * 2 + 1] = a01;
    aw[bbase + (size_t)(i0 + ti * 2 + 1) * CC + j0 + tj * 2    ] = a10;
    aw[bbase + (size_t)(i0 + ti * 2 + 1) * CC + j0 + tj * 2 + 1] = a11;
}

// ---------------- softmax over 256-wide rows ----------------
__global__ void softmax256_kernel(float* __restrict__ p) {
    __shared__ float red[256];
    int t = threadIdx.x;
    float* pr = p + (size_t)blockIdx.x * 256;
    float v = pr[t];
    red[t] = v;
    __syncthreads();
    for (int o = 128; o; o >>= 1) { if (t < o) red[t] = fmaxf(red[t], red[t + o]); __syncthreads(); }
    float mx = red[0];
    __syncthreads();
    float e = expf(v - mx);
    red[t] = e;
    __syncthreads();
    for (int o = 128; o; o >>= 1) { if (t < o) red[t] += red[t + o]; __syncthreads(); }
    pr[t] = e / red[0];
}

// ---------------- row attention context: ctx = p @ v (half out) ----------------
__global__ void __launch_bounds__(256) row_ctx_kernel(
    const float* __restrict__ p, const __half* __restrict__ v, __half* __restrict__ ctx)
{
    int i0 = blockIdx.x * 32;
    int h = blockIdx.y;
    int r = blockIdx.z;
    int tid = threadIdx.x;
    int tx = tid & 63, ty = tid >> 6;
    __shared__ float ps[32][33];
    __shared__ float vs[32][65];
    float acc[8];
    #pragma unroll
    for (int u = 0; u < 8; u++) acc[u] = 0.f;

    int lrow = tid >> 3, lcol = (tid & 7) * 8;
    for (int jc = 0; jc < CC; jc += 32) {
        {
            int row = tid >> 3, col = (tid & 7) * 4;
            float4 vp = *(const float4*)(p + (size_t)h * CC * CC + (size_t)(i0 + row) * CC + jc + col);
            ps[row][col] = vp.x; ps[row][col + 1] = vp.y; ps[row][col + 2] = vp.z; ps[row][col + 3] = vp.w;
        }
        uint4 rv = *(const uint4*)(v + ((size_t)((r * CC + jc + lrow) * HH + h)) * DD + lcol);
        unpack8(&vs[lrow][lcol], rv);
        __syncthreads();
        #pragma unroll 8
        for (int j = 0; j < 32; j++) {
            float vv = vs[j][tx];
            #pragma unroll
            for (int u = 0; u < 8; u++)
                acc[u] = fmaf(ps[ty * 8 + u][j], vv, acc[u]);
        }
        __syncthreads();
    }
    #pragma unroll
    for (int u = 0; u < 8; u++)
        ctx[((size_t)((r * CC + i0 + ty * 8 + u) * HH + h)) * DD + tx] = __float2half(acc[u]);
}

// ---------------- column attention scores ----------------
__global__ void __launch_bounds__(256) col_scores_kernel(
    const __half* __restrict__ q, const __half* __restrict__ k, float* __restrict__ aw)
{
    int c = blockIdx.x, h = blockIdx.y;
    __shared__ float qs[64][65];
    __shared__ float ks[64][65];
    int tid = threadIdx.x;
    #pragma unroll
    for (int c4 = 0; c4 < 2; c4++) {
        int e = tid + 256 * c4;
        int row = e >> 3, col = (e & 7) * 8;
        uint4 rq = *(const uint4*)(q + ((size_t)((row * CC + c) * HH + h)) * DD + col);
        unpack8(&qs[row][col], rq);
        uint4 rk = *(const uint4*)(k + ((size_t)((row * CC + c) * HH + h)) * DD + col);
        unpack8(&ks[row][col], rk);
    }
    __syncthreads();
    int j = tid & 63, ib = (tid >> 6) * 16;
    float acc[16];
    #pragma unroll
    for (int u = 0; u < 16; u++) acc[u] = 0.f;
    #pragma unroll 4
    for (int d = 0; d < DD; d++) {
        float kv = ks[j][d];
        #pragma unroll
        for (int u = 0; u < 16; u++)
            acc[u] = fmaf(qs[ib + u][d], kv, acc[u]);
    }
    size_t bbase = ((size_t)h * CC + c) * RR * RR;
    #pragma unroll
    for (int u = 0; u < 16; u++)
        aw[bbase + (size_t)(ib + u) * RR + j] = acc[u];
}

// ---------------- softmax over 64-wide rows ----------------
__global__ void softmax64_kernel(float* __restrict__ p, int nrows) {
    int warp = (blockIdx.x * blockDim.x + threadIdx.x) >> 5;
    int lane = threadIdx.x & 31;
    if (warp >= nrows) return;
    float* pr = p + (size_t)warp * 64;
    float a = pr[lane], b = pr[lane + 32];
    float mx = fmaxf(a, b);
    #pragma unroll
    for (int o = 16; o; o >>= 1) mx = fmaxf(mx, __shfl_xor_sync(0xffffffffu, mx, o));
    a = expf(a - mx); b = expf(b - mx);
    float s = a + b;
    #pragma unroll
    for (int o = 16; o; o >>= 1) s += __shfl_xor_sync(0xffffffffu, s, o);
    float inv = 1.0f / s;
    pr[lane] = a * inv; pr[lane + 32] = b * inv;
}

// ---------------- column attention context (half out) ----------------
__global__ void __launch_bounds__(256) col_ctx_kernel(
    const float* __restrict__ p, const __half* __restrict__ v, __half* __restrict__ ctx)
{
    int c = blockIdx.x, h = blockIdx.y;
    __shared__ float ps[64][65];
    __shared__ float vs[64][65];
    int tid = threadIdx.x;
    size_t pbase = ((size_t)h * CC + c) * RR * RR;
    #pragma unroll
    for (int c4 = 0; c4 < 4; c4++) {
        int e4 = tid + 256 * c4;
        int row = e4 >> 4, col = (e4 & 15) * 4;
        float4 vp = *(const float4*)(p + pbase + (size_t)row * RR + col);
        ps[row][col] = vp.x; ps[row][col + 1] = vp.y; ps[row][col + 2] = vp.z; ps[row][col + 3] = vp.w;
    }
    #pragma unroll
    for (int c4 = 0; c4 < 2; c4++) {
        int e = tid + 256 * c4;
        int row = e >> 3, col = (e & 7) * 8;
        uint4 rv = *(const uint4*)(v + ((size_t)((row * CC + c) * HH + h)) * DD + col);
        unpack8(&vs[row][col], rv);
    }
    __syncthreads();
    int d = tid & 63, ib = (tid >> 6) * 16;
    float acc[16];
    #pragma unroll
    for (int u = 0; u < 16; u++) acc[u] = 0.f;
    #pragma unroll 4
    for (int j = 0; j < RR; j++) {
        float vv = vs[j][d];
        #pragma unroll
        for (int u = 0; u < 16; u++)
            acc[u] = fmaf(ps[ib + u][j], vv, acc[u]);
    }
    #pragma unroll
    for (int u = 0; u < 16; u++)
        ctx[((size_t)(((ib + u) * CC + c) * HH + h)) * DD + d] = __float2half(acc[u]);
}

// ---------------- host driver ----------------
#define GEMM_SMEM (NSTAGE * 2 * TILE_H * 2)   // 61440 bytes

static void run_gemm(const __half* A, const __half* BT, const float* bias, const float* res,
                     float* Cf, __half* Ch, int M, int N, int K, float scale, int gelu) {
    dim3 grid(N / 128, M / 128);
    mma_gemm_f16<<<grid, 256, GEMM_SMEM>>>(A, BT, bias, res, Cf, Ch, M, N, K, scale, gelu);
}

extern "C" void kernel_launch(void* const* d_in, const int* in_sizes, int n_in,
                              void* d_out, int out_size) {
    const float* x_in = (const float*)d_in[0];
    const float* rq_w = (const float*)d_in[1];  const float* rq_b = (const float*)d_in[2];
    const float* rk_w = (const float*)d_in[3];  const float* rk_b = (const float*)d_in[4];
    const float* rv_w = (const float*)d_in[5];  const float* rv_b = (const float*)d_in[6];
    const float* ro_w = (const float*)d_in[7];  const float* ro_b = (const float*)d_in[8];
    const float* cq_w = (const float*)d_in[9];  const float* cq_b = (const float*)d_in[10];
    const float* ck_w = (const float*)d_in[11]; const float* ck_b = (const float*)d_in[12];
    const float* cv_w = (const float*)d_in[13]; const float* cv_b = (const float*)d_in[14];
    const float* co_w = (const float*)d_in[15]; const float* co_b = (const float*)d_in[16];
    const float* f1_w = (const float*)d_in[17]; const float* f1_b = (const float*)d_in[18];
    const float* f2_w = (const float*)d_in[19]; const float* f2_b = (const float*)d_in[20];
    const float* ln1_s = (const float*)d_in[21]; const float* ln1_b = (const float*)d_in[22];
    const float* ln2_s = (const float*)d_in[23]; const float* ln2_b = (const float*)d_in[24];
    const float* ln3_s = (const float*)d_in[25]; const float* ln3_b = (const float*)d_in[26];

    float *px, *paw;
    void *vh, *vq, *vk, *vv, *vctx, *vffn, *vwt;
    cudaGetSymbolAddress((void**)&px,   g_x);
    cudaGetSymbolAddress(&vh,   g_h);
    cudaGetSymbolAddress(&vq,   g_q);
    cudaGetSymbolAddress(&vk,   g_k);
    cudaGetSymbolAddress(&vv,   g_v);
    cudaGetSymbolAddress(&vctx, g_ctx);
    cudaGetSymbolAddress((void**)&paw,  g_aw);
    cudaGetSymbolAddress(&vffn, g_ffn);
    cudaGetSymbolAddress(&vwt,  g_wt);
    __half* ph   = (__half*)vh;
    __half* pq   = (__half*)vq;
    __half* pk   = (__half*)vk;
    __half* pv   = (__half*)vv;
    __half* pctx = (__half*)vctx;
    __half* pffn = (__half*)vffn;
    __half* pwt  = (__half*)vwt;

    cudaFuncSetAttribute(mma_gemm_f16, cudaFuncAttributeMaxDynamicSharedMemorySize, GEMM_SMEM);

    // transposed half weights
    const size_t WEE = (size_t)EE * EE;
    __half* rqT = pwt + 0 * WEE;  __half* rkT = pwt + 1 * WEE;
    __half* rvT = pwt + 2 * WEE;  __half* roT = pwt + 3 * WEE;
    __half* cqT = pwt + 4 * WEE;  __half* ckT = pwt + 5 * WEE;
    __half* cvT = pwt + 6 * WEE;  __half* coT = pwt + 7 * WEE;
    __half* f1T = pwt + 8 * WEE;                     // [F][E]
    __half* f2T = f1T + (size_t)EE * FF;             // [E][F]

    { dim3 b(32, 8);
      dim3 gE(EE / 32, EE / 32);
      transpose_kernel<<<gE, b>>>(rq_w, rqT, EE, EE);
      transpose_kernel<<<gE, b>>>(rk_w, rkT, EE, EE);
      transpose_kernel<<<gE, b>>>(rv_w, rvT, EE, EE);
      transpose_kernel<<<gE, b>>>(ro_w, roT, EE, EE);
      transpose_kernel<<<gE, b>>>(cq_w, cqT, EE, EE);
      transpose_kernel<<<gE, b>>>(ck_w, ckT, EE, EE);
      transpose_kernel<<<gE, b>>>(cv_w, cvT, EE, EE);
      transpose_kernel<<<gE, b>>>(co_w, coT, EE, EE);
      dim3 gF1(FF / 32, EE / 32);
      transpose_kernel<<<gF1, b>>>(f1_w, f1T, EE, FF);
      dim3 gF2(EE / 32, FF / 32);
      transpose_kernel<<<gF2, b>>>(f2_w, f2T, FF, EE);
    }

    const float row_scale = 0.015625f;  // D^-0.5 * R^-0.5
    const float col_scale = 0.125f;     // D^-0.5

    cudaMemcpyAsync(px, x_in, (size_t)MM * EE * sizeof(float), cudaMemcpyDeviceToDevice);

    // ===== row attention =====
    ln_kernel<<<MM, 256>>>(px, ln1_s, ln1_b, ph);
    run_gemm(ph, rqT, rq_b, nullptr, nullptr, pq, MM, EE, EE, row_scale, 0);
    run_gemm(ph, rkT, rk_b, nullptr, nullptr, pk, MM, EE, EE, 1.0f, 0);
    run_gemm(ph, rvT, rv_b, nullptr, nullptr, pv, MM, EE, EE, 1.0f, 0);
    { dim3 g(CC / 32, CC / 32, HH); row_scores_kernel<<<g, 256>>>(pq, pk, paw); }
    softmax256_kernel<<<HH * CC, 256>>>(paw);
    { dim3 g(CC / 32, HH, RR); row_ctx_kernel<<<g, 256>>>(paw, pv, pctx); }
    run_gemm(pctx, roT, ro_b, px, px, nullptr, MM, EE, EE, 1.0f, 0);

    // ===== column attention =====
    ln_kernel<<<MM, 256>>>(px, ln2_s, ln2_b, ph);
    run_gemm(ph, cqT, cq_b, nullptr, nullptr, pq, MM, EE, EE, col_scale, 0);
    run_gemm(ph, ckT, ck_b, nullptr, nullptr, pk, MM, EE, EE, 1.0f, 0);
    run_gemm(ph, cvT, cv_b, nullptr, nullptr, pv, MM, EE, EE, 1.0f, 0);
    { dim3 g(CC, HH); col_scores_kernel<<<g, 256>>>(pq, pk, paw); }
    { int nrows = HH * CC * RR; softmax64_kernel<<<(nrows * 32 + 255) / 256, 256>>>(paw, nrows); }
    { dim3 g(CC, HH); col_ctx_kernel<<<g, 256>>>(paw, pv, pctx); }
    run_gemm(pctx, coT, co_b, px, px, nullptr, MM, EE, EE, 1.0f, 0);

    // ===== FFN =====
    ln_kernel<<<MM, 256>>>(px, ln3_s, ln3_b, ph);
    run_gemm(ph, f1T, f1_b, nullptr, nullptr, pffn, MM, FF, EE, 1.0f, 1);
    run_gemm(pffn, f2T, f2_b, px, (float*)d_out, nullptr, MM, EE, FF, 1.0f, 0);
}